// round 1
// baseline (speedup 1.0000x reference)
#include <cuda_runtime.h>

#define B_  2
#define C_  512
#define NH  8
#define D_  64
#define S_  2304          // 48*48
#define SCALE 0.125f      // 1/sqrt(64)

// Scratch (no allocations allowed) ------------------------------------------
__device__ float g_q[B_ * NH * D_ * S_];    // [b][n][d][s]
__device__ float g_k[B_ * NH * D_ * S_];    // [b][n][d][s]
__device__ float g_v[B_ * NH * S_ * D_];    // [b][n][s][d]
__device__ float g_attn[B_ * S_ * NH * D_]; // [b][s][n*64+d]

// ---------------------------------------------------------------------------
// QKV projection: out[b,n,s,d] = sum_c x[b,c,s] * W[n,d,c] + bias[n,d]
// grid: (36 s-tiles, 16 b*n, 3 proj), block 256 (16x16), 4x4 micro-tile.
// tx -> s direction, ty -> d direction.
// ---------------------------------------------------------------------------
__global__ __launch_bounds__(256) void proj_kernel(
    const float* __restrict__ x,
    const float* __restrict__ Wq, const float* __restrict__ bq,
    const float* __restrict__ Wk, const float* __restrict__ bk,
    const float* __restrict__ Wv, const float* __restrict__ bv)
{
    const int p  = blockIdx.z;
    const int bn = blockIdx.y;
    const int b  = bn >> 3, n = bn & 7;
    const int s0 = blockIdx.x * 64;

    const float* W    = (p == 0) ? Wq : (p == 1) ? Wk : Wv;
    const float* bias = (p == 0) ? bq : (p == 1) ? bk : bv;

    __shared__ float Xs[32][64];   // [c'][s']
    __shared__ float Wst[32][65];  // [c'][d'] (padded: transposed store)

    const int tid = threadIdx.x;
    const int tx = tid & 15, ty = tid >> 4;

    float acc[4][4] = {};
    const float* xb = x + (size_t)b * C_ * S_ + s0;
    const float* Wn = W + n * D_ * C_;

    for (int k0 = 0; k0 < C_; k0 += 32) {
        #pragma unroll
        for (int r = 0; r < 8; r++) {          // X tile: coalesced in s
            int idx = tid + r * 256;
            int c = idx >> 6, s = idx & 63;
            Xs[c][s] = xb[(size_t)(k0 + c) * S_ + s];
        }
        #pragma unroll
        for (int r = 0; r < 8; r++) {          // W tile: coalesced in c, store transposed
            int idx = tid + r * 256;
            int d = idx >> 5, c = idx & 31;
            Wst[c][d] = Wn[d * C_ + k0 + c];
        }
        __syncthreads();

        #pragma unroll 8
        for (int kk = 0; kk < 32; kk++) {
            float4 a4 = *(const float4*)&Xs[kk][tx * 4];
            float a[4] = {a4.x, a4.y, a4.z, a4.w};
            float bb[4];
            #pragma unroll
            for (int i = 0; i < 4; i++) bb[i] = Wst[kk][ty * 4 + i];
            #pragma unroll
            for (int i = 0; i < 4; i++)
                #pragma unroll
                for (int j = 0; j < 4; j++)
                    acc[i][j] += bb[i] * a[j];
        }
        __syncthreads();
    }

    if (p < 2) {
        // Q/K stored [d][s] for conflict-free attention GEMM reads
        float* g = ((p == 0) ? g_q : g_k) + (size_t)(b * NH + n) * D_ * S_;
        #pragma unroll
        for (int i = 0; i < 4; i++) {
            float bi = bias[n * D_ + ty * 4 + i];
            float4 v4 = make_float4(acc[i][0] + bi, acc[i][1] + bi,
                                    acc[i][2] + bi, acc[i][3] + bi);
            *(float4*)&g[(size_t)(ty * 4 + i) * S_ + s0 + tx * 4] = v4;
        }
    } else {
        // V stored [s][d]
        float* g = g_v + (size_t)(b * NH + n) * S_ * D_;
        #pragma unroll
        for (int j = 0; j < 4; j++) {
            float4 v4 = make_float4(acc[0][j] + bias[n * D_ + ty * 4 + 0],
                                    acc[1][j] + bias[n * D_ + ty * 4 + 1],
                                    acc[2][j] + bias[n * D_ + ty * 4 + 2],
                                    acc[3][j] + bias[n * D_ + ty * 4 + 3]);
            *(float4*)&g[(size_t)(s0 + tx * 4 + j) * D_ + ty * 4] = v4;
        }
    }
}

// ---------------------------------------------------------------------------
// Flash attention, fp32, 64-row q-tile per CTA, 64-wide kv tiles.
// grid: (36 q-tiles, 16 b*n), block 256 (16x16). ty->q rows, tx->k / d cols.
// smem exactly 48KB: Q^T, K^T (reused for P), V.
// ---------------------------------------------------------------------------
__global__ __launch_bounds__(256) void attn_kernel()
{
    __shared__ float Qst[64][64];  // [d][q], pre-scaled
    __shared__ float KPs[64][64];  // phase 1: K^T [d][k]; phase 2: P [q][k]
    __shared__ float Vs[64][64];   // [k][d]

    const int bn = blockIdx.y;
    const int b = bn >> 3, n = bn & 7;
    const int q0 = blockIdx.x * 64;
    const int tid = threadIdx.x;
    const int tx = tid & 15, ty = tid >> 4;

    const float* Q = g_q + (size_t)(b * NH + n) * D_ * S_;
    const float* K = g_k + (size_t)(b * NH + n) * D_ * S_;
    const float* V = g_v + (size_t)(b * NH + n) * S_ * D_;

    #pragma unroll
    for (int r = 0; r < 16; r++) {
        int idx = tid + r * 256;
        int d = idx >> 6, qq = idx & 63;
        Qst[d][qq] = Q[(size_t)d * S_ + q0 + qq] * SCALE;
    }

    float m[4], l[4], O[4][4];
    #pragma unroll
    for (int i = 0; i < 4; i++) {
        m[i] = -1e30f; l[i] = 0.f;
        #pragma unroll
        for (int j = 0; j < 4; j++) O[i][j] = 0.f;
    }

    for (int k0 = 0; k0 < S_; k0 += 64) {
        #pragma unroll
        for (int r = 0; r < 16; r++) {
            int idx = tid + r * 256;
            int aa = idx >> 6, bbq = idx & 63;
            KPs[aa][bbq] = K[(size_t)aa * S_ + k0 + bbq];  // K^T tile [d][k]
            Vs[aa][bbq]  = V[(size_t)(k0 + aa) * D_ + bbq]; // V tile [k][d]
        }
        __syncthreads();

        // S = (Q*scale) K^T  -- both operands [d][*]-major: LDS.128 clean
        float Sc[4][4] = {};
        #pragma unroll 8
        for (int dd = 0; dd < 64; dd++) {
            float4 a4 = *(const float4*)&Qst[dd][ty * 4];
            float4 b4 = *(const float4*)&KPs[dd][tx * 4];
            float a[4] = {a4.x, a4.y, a4.z, a4.w};
            float bb[4] = {b4.x, b4.y, b4.z, b4.w};
            #pragma unroll
            for (int i = 0; i < 4; i++)
                #pragma unroll
                for (int j = 0; j < 4; j++)
                    Sc[i][j] += a[i] * bb[j];
        }

        // online softmax (rows = q = ty*4+i, reduce across 16 tx lanes)
        float mt[4], rs[4], mn[4], corr[4];
        #pragma unroll
        for (int i = 0; i < 4; i++) {
            mt[i] = fmaxf(fmaxf(Sc[i][0], Sc[i][1]), fmaxf(Sc[i][2], Sc[i][3]));
        }
        #pragma unroll
        for (int off = 8; off > 0; off >>= 1)
            #pragma unroll
            for (int i = 0; i < 4; i++)
                mt[i] = fmaxf(mt[i], __shfl_xor_sync(0xffffffffu, mt[i], off, 16));
        #pragma unroll
        for (int i = 0; i < 4; i++) {
            mn[i]   = fmaxf(m[i], mt[i]);
            corr[i] = __expf(m[i] - mn[i]);
            float s = 0.f;
            #pragma unroll
            for (int j = 0; j < 4; j++) {
                Sc[i][j] = __expf(Sc[i][j] - mn[i]);
                s += Sc[i][j];
            }
            rs[i] = s;
        }
        #pragma unroll
        for (int off = 8; off > 0; off >>= 1)
            #pragma unroll
            for (int i = 0; i < 4; i++)
                rs[i] += __shfl_xor_sync(0xffffffffu, rs[i], off, 16);
        #pragma unroll
        for (int i = 0; i < 4; i++) {
            l[i] = l[i] * corr[i] + rs[i];
            m[i] = mn[i];
            #pragma unroll
            for (int j = 0; j < 4; j++) O[i][j] *= corr[i];
        }

        __syncthreads();                      // everyone done reading K
        #pragma unroll
        for (int i = 0; i < 4; i++)           // P -> smem (reuse K region)
            *(float4*)&KPs[ty * 4 + i][tx * 4] =
                make_float4(Sc[i][0], Sc[i][1], Sc[i][2], Sc[i][3]);
        __syncthreads();

        // O += P @ V
        #pragma unroll 8
        for (int kk = 0; kk < 64; kk++) {
            float4 b4 = *(const float4*)&Vs[kk][tx * 4];
            float bb[4] = {b4.x, b4.y, b4.z, b4.w};
            float a[4];
            #pragma unroll
            for (int i = 0; i < 4; i++) a[i] = KPs[ty * 4 + i][kk];
            #pragma unroll
            for (int i = 0; i < 4; i++)
                #pragma unroll
                for (int j = 0; j < 4; j++)
                    O[i][j] += a[i] * bb[j];
        }
        __syncthreads();
    }

    // epilogue: normalize, write [b][s][n*64+d] (head concat contiguous)
    float* A = g_attn + ((size_t)b * S_ + q0) * (NH * D_) + n * D_;
    #pragma unroll
    for (int i = 0; i < 4; i++) {
        float inv = 1.f / l[i];
        *(float4*)&A[(size_t)(ty * 4 + i) * (NH * D_) + tx * 4] =
            make_float4(O[i][0] * inv, O[i][1] * inv, O[i][2] * inv, O[i][3] * inv);
    }
}

// ---------------------------------------------------------------------------
// Output projection: out[b,c,s] = bo[c] + sum_j attn[b,s,j] * Wo[c,j]
// grid: (36 s-tiles, 8 c-tiles, 2 batch). tx->s, ty->c (coalesced stores).
// ---------------------------------------------------------------------------
__global__ __launch_bounds__(256) void oproj_kernel(
    const float* __restrict__ Wo, const float* __restrict__ bo,
    float* __restrict__ out)
{
    const int b  = blockIdx.z;
    const int c0 = blockIdx.y * 64;
    const int s0 = blockIdx.x * 64;

    __shared__ float Ast[32][65];  // [j'][s']
    __shared__ float Wst[32][65];  // [j'][c']

    const int tid = threadIdx.x;
    const int tx = tid & 15, ty = tid >> 4;

    float acc[4][4] = {};
    const float* A = g_attn + ((size_t)b * S_ + s0) * C_;

    for (int j0 = 0; j0 < C_; j0 += 32) {
        #pragma unroll
        for (int r = 0; r < 8; r++) {
            int idx = tid + r * 256;
            int rr = idx >> 5, jj = idx & 31;
            Ast[jj][rr] = A[(size_t)rr * C_ + j0 + jj];
            Wst[jj][rr] = Wo[(size_t)(c0 + rr) * C_ + j0 + jj];
        }
        __syncthreads();

        #pragma unroll 8
        for (int jj = 0; jj < 32; jj++) {
            float a[4], bb[4];
            #pragma unroll
            for (int j = 0; j < 4; j++) a[j] = Ast[jj][tx * 4 + j];
            #pragma unroll
            for (int i = 0; i < 4; i++) bb[i] = Wst[jj][ty * 4 + i];
            #pragma unroll
            for (int i = 0; i < 4; i++)
                #pragma unroll
                for (int j = 0; j < 4; j++)
                    acc[i][j] += bb[i] * a[j];
        }
        __syncthreads();
    }

    float* ob = out + ((size_t)b * C_ + c0) * S_ + s0;
    #pragma unroll
    for (int i = 0; i < 4; i++) {
        float bi = bo[c0 + ty * 4 + i];
        *(float4*)&ob[(size_t)(ty * 4 + i) * S_ + tx * 4] =
            make_float4(acc[i][0] + bi, acc[i][1] + bi,
                        acc[i][2] + bi, acc[i][3] + bi);
    }
}

// ---------------------------------------------------------------------------
extern "C" void kernel_launch(void* const* d_in, const int* in_sizes, int n_in,
                              void* d_out, int out_size)
{
    const float* x  = (const float*)d_in[0];
    const float* Wq = (const float*)d_in[1];
    const float* bq = (const float*)d_in[2];
    const float* Wk = (const float*)d_in[3];
    const float* bk = (const float*)d_in[4];
    const float* Wv = (const float*)d_in[5];
    const float* bv = (const float*)d_in[6];
    const float* Wo = (const float*)d_in[7];
    const float* bo = (const float*)d_in[8];
    float* out = (float*)d_out;

    proj_kernel <<<dim3(S_ / 64, B_ * NH, 3), 256>>>(x, Wq, bq, Wk, bk, Wv, bv);
    attn_kernel <<<dim3(S_ / 64, B_ * NH),    256>>>();
    oproj_kernel<<<dim3(S_ / 64, C_ / 64, B_), 256>>>(Wo, bo, out);
}

// round 2
// speedup vs baseline: 1.0127x; 1.0127x over previous
#include <cuda_runtime.h>

#define B_  2
#define C_  512
#define NH  8
#define D_  64
#define S_  2304          // 48*48
#define SCALE 0.125f      // 1/sqrt(64)

typedef unsigned long long u64;

// packed fp32x2 helpers (FFMA2 path is PTX-only per sm_103a SASS spec)
__device__ __forceinline__ void fma2(u64& d, u64 a, u64 b) {
    asm("fma.rn.f32x2 %0, %1, %2, %0;" : "+l"(d) : "l"(a), "l"(b));
}
__device__ __forceinline__ void mul2(u64& d, u64 a, u64 b) {
    asm("mul.rn.f32x2 %0, %1, %2;" : "=l"(d) : "l"(a), "l"(b));
}
__device__ __forceinline__ u64 bc2(float x) {
    u64 r; unsigned xi = __float_as_uint(x);
    asm("mov.b64 %0, {%1, %1};" : "=l"(r) : "r"(xi));
    return r;
}
__device__ __forceinline__ u64 pk2(float lo, float hi) {
    u64 r;
    asm("mov.b64 %0, {%1, %2};" : "=l"(r)
        : "r"(__float_as_uint(lo)), "r"(__float_as_uint(hi)));
    return r;
}
__device__ __forceinline__ float2 up2(u64 v) {
    unsigned lo, hi;
    asm("mov.b64 {%0, %1}, %2;" : "=r"(lo), "=r"(hi) : "l"(v));
    return make_float2(__uint_as_float(lo), __uint_as_float(hi));
}

// Scratch (no allocations allowed) ------------------------------------------
__device__ float g_q[B_ * NH * D_ * S_];    // [b][n][d][s]
__device__ float g_k[B_ * NH * D_ * S_];    // [b][n][d][s]
__device__ float g_v[B_ * NH * S_ * D_];    // [b][n][s][d]
__device__ float g_attn[B_ * S_ * NH * D_]; // [b][s][n*64+d]

// ---------------------------------------------------------------------------
// QKV projection: out[b,n,s,d] = sum_c x[b,c,s] * W[n,d,c] + bias[n,d]
// ---------------------------------------------------------------------------
__global__ __launch_bounds__(256) void proj_kernel(
    const float* __restrict__ x,
    const float* __restrict__ Wq, const float* __restrict__ bq,
    const float* __restrict__ Wk, const float* __restrict__ bk,
    const float* __restrict__ Wv, const float* __restrict__ bv)
{
    const int p  = blockIdx.z;
    const int bn = blockIdx.y;
    const int b  = bn >> 3, n = bn & 7;
    const int s0 = blockIdx.x * 64;

    const float* W    = (p == 0) ? Wq : (p == 1) ? Wk : Wv;
    const float* bias = (p == 0) ? bq : (p == 1) ? bk : bv;

    __shared__ float Xs[32][64];   // [c'][s']
    __shared__ float Wst[32][65];  // [c'][d'] (padded, transposed store)

    const int tid = threadIdx.x;
    const int tx = tid & 15, ty = tid >> 4;

    u64 acc2[4][2] = {};
    const float* xb = x + (size_t)b * C_ * S_ + s0;
    const float* Wn = W + n * D_ * C_;

    for (int k0 = 0; k0 < C_; k0 += 32) {
        #pragma unroll
        for (int r = 0; r < 8; r++) {
            int idx = tid + r * 256;
            int c = idx >> 6, s = idx & 63;
            Xs[c][s] = xb[(size_t)(k0 + c) * S_ + s];
        }
        #pragma unroll
        for (int r = 0; r < 8; r++) {
            int idx = tid + r * 256;
            int d = idx >> 5, c = idx & 31;
            Wst[c][d] = Wn[d * C_ + k0 + c];
        }
        __syncthreads();

        #pragma unroll 8
        for (int kk = 0; kk < 32; kk++) {
            float4 a4 = *(const float4*)&Xs[kk][tx * 4];
            u64 a20 = pk2(a4.x, a4.y), a21 = pk2(a4.z, a4.w);
            #pragma unroll
            for (int i = 0; i < 4; i++) {
                u64 b2 = bc2(Wst[kk][ty * 4 + i]);
                fma2(acc2[i][0], b2, a20);
                fma2(acc2[i][1], b2, a21);
            }
        }
        __syncthreads();
    }

    if (p < 2) {
        float* g = ((p == 0) ? g_q : g_k) + (size_t)(b * NH + n) * D_ * S_;
        #pragma unroll
        for (int i = 0; i < 4; i++) {
            float bi = bias[n * D_ + ty * 4 + i];
            float2 p0 = up2(acc2[i][0]), p1 = up2(acc2[i][1]);
            *(float4*)&g[(size_t)(ty * 4 + i) * S_ + s0 + tx * 4] =
                make_float4(p0.x + bi, p0.y + bi, p1.x + bi, p1.y + bi);
        }
    } else {
        float* g = g_v + (size_t)(b * NH + n) * S_ * D_;
        float bi[4];
        #pragma unroll
        for (int i = 0; i < 4; i++) bi[i] = bias[n * D_ + ty * 4 + i];
        float r[4][4];
        #pragma unroll
        for (int i = 0; i < 4; i++) {
            float2 p0 = up2(acc2[i][0]), p1 = up2(acc2[i][1]);
            r[i][0] = p0.x + bi[i]; r[i][1] = p0.y + bi[i];
            r[i][2] = p1.x + bi[i]; r[i][3] = p1.y + bi[i];
        }
        #pragma unroll
        for (int j = 0; j < 4; j++) {
            *(float4*)&g[(size_t)(s0 + tx * 4 + j) * D_ + ty * 4] =
                make_float4(r[0][j], r[1][j], r[2][j], r[3][j]);
        }
    }
}

// ---------------------------------------------------------------------------
// Flash attention, fp32 packed f32x2, 64-row q-tile per CTA, 64-wide kv tiles.
// ---------------------------------------------------------------------------
__global__ __launch_bounds__(256) void attn_kernel()
{
    __shared__ float Qst[64][64];  // [d][q], pre-scaled
    __shared__ float KPs[64][64];  // phase 1: K^T [d][k]; phase 2: P [q][k]
    __shared__ float Vs[64][64];   // [k][d]

    const int bn = blockIdx.y;
    const int b = bn >> 3, n = bn & 7;
    const int q0 = blockIdx.x * 64;
    const int tid = threadIdx.x;
    const int tx = tid & 15, ty = tid >> 4;

    const float* Q = g_q + (size_t)(b * NH + n) * D_ * S_;
    const float* K = g_k + (size_t)(b * NH + n) * D_ * S_;
    const float* V = g_v + (size_t)(b * NH + n) * S_ * D_;

    #pragma unroll
    for (int r = 0; r < 16; r++) {
        int idx = tid + r * 256;
        int d = idx >> 6, qq = idx & 63;
        Qst[d][qq] = Q[(size_t)d * S_ + q0 + qq] * SCALE;
    }

    float m[4], l[4];
    u64 O2[4][2];
    #pragma unroll
    for (int i = 0; i < 4; i++) {
        m[i] = -1e30f; l[i] = 0.f;
        O2[i][0] = 0ull; O2[i][1] = 0ull;
    }

    for (int k0 = 0; k0 < S_; k0 += 64) {
        #pragma unroll
        for (int r = 0; r < 16; r++) {
            int idx = tid + r * 256;
            int aa = idx >> 6, bbq = idx & 63;
            KPs[aa][bbq] = K[(size_t)aa * S_ + k0 + bbq];
            Vs[aa][bbq]  = V[(size_t)(k0 + aa) * D_ + bbq];
        }
        __syncthreads();

        // S = (Q*scale) @ K^T
        u64 S2[4][2] = {};
        #pragma unroll 8
        for (int dd = 0; dd < 64; dd++) {
            float4 a4 = *(const float4*)&Qst[dd][ty * 4];
            float4 b4 = *(const float4*)&KPs[dd][tx * 4];
            u64 b20 = pk2(b4.x, b4.y), b21 = pk2(b4.z, b4.w);
            float a[4] = {a4.x, a4.y, a4.z, a4.w};
            #pragma unroll
            for (int i = 0; i < 4; i++) {
                u64 a2 = bc2(a[i]);
                fma2(S2[i][0], a2, b20);
                fma2(S2[i][1], a2, b21);
            }
        }
        float Sc[4][4];
        #pragma unroll
        for (int i = 0; i < 4; i++) {
            float2 p0 = up2(S2[i][0]), p1 = up2(S2[i][1]);
            Sc[i][0] = p0.x; Sc[i][1] = p0.y; Sc[i][2] = p1.x; Sc[i][3] = p1.y;
        }

        // online softmax (rows = ty*4+i, reduce across 16 tx lanes)
        float mt[4], rs[4], mn[4], corr[4];
        #pragma unroll
        for (int i = 0; i < 4; i++)
            mt[i] = fmaxf(fmaxf(Sc[i][0], Sc[i][1]), fmaxf(Sc[i][2], Sc[i][3]));
        #pragma unroll
        for (int off = 8; off > 0; off >>= 1)
            #pragma unroll
            for (int i = 0; i < 4; i++)
                mt[i] = fmaxf(mt[i], __shfl_xor_sync(0xffffffffu, mt[i], off, 16));
        #pragma unroll
        for (int i = 0; i < 4; i++) {
            mn[i]   = fmaxf(m[i], mt[i]);
            corr[i] = __expf(m[i] - mn[i]);
            float s = 0.f;
            #pragma unroll
            for (int j = 0; j < 4; j++) {
                Sc[i][j] = __expf(Sc[i][j] - mn[i]);
                s += Sc[i][j];
            }
            rs[i] = s;
        }
        #pragma unroll
        for (int off = 8; off > 0; off >>= 1)
            #pragma unroll
            for (int i = 0; i < 4; i++)
                rs[i] += __shfl_xor_sync(0xffffffffu, rs[i], off, 16);
        #pragma unroll
        for (int i = 0; i < 4; i++) {
            l[i] = l[i] * corr[i] + rs[i];
            m[i] = mn[i];
            u64 c2 = bc2(corr[i]);
            mul2(O2[i][0], O2[i][0], c2);
            mul2(O2[i][1], O2[i][1], c2);
        }

        __syncthreads();                      // everyone done reading K
        #pragma unroll
        for (int i = 0; i < 4; i++)
            *(float4*)&KPs[ty * 4 + i][tx * 4] =
                make_float4(Sc[i][0], Sc[i][1], Sc[i][2], Sc[i][3]);
        __syncthreads();

        // O += P @ V
        #pragma unroll 8
        for (int kk = 0; kk < 64; kk++) {
            float4 b4 = *(const float4*)&Vs[kk][tx * 4];
            u64 b20 = pk2(b4.x, b4.y), b21 = pk2(b4.z, b4.w);
            #pragma unroll
            for (int i = 0; i < 4; i++) {
                u64 a2 = bc2(KPs[ty * 4 + i][kk]);
                fma2(O2[i][0], a2, b20);
                fma2(O2[i][1], a2, b21);
            }
        }
        __syncthreads();
    }

    // epilogue: normalize, write [b][s][n*64+d]
    float* A = g_attn + ((size_t)b * S_ + q0) * (NH * D_) + n * D_;
    #pragma unroll
    for (int i = 0; i < 4; i++) {
        u64 inv2 = bc2(1.f / l[i]);
        mul2(O2[i][0], O2[i][0], inv2);
        mul2(O2[i][1], O2[i][1], inv2);
        float2 p0 = up2(O2[i][0]), p1 = up2(O2[i][1]);
        *(float4*)&A[(size_t)(ty * 4 + i) * (NH * D_) + tx * 4] =
            make_float4(p0.x, p0.y, p1.x, p1.y);
    }
}

// ---------------------------------------------------------------------------
// Output projection: out[b,c,s] = bo[c] + sum_j attn[b,s,j] * Wo[c,j]
// ---------------------------------------------------------------------------
__global__ __launch_bounds__(256) void oproj_kernel(
    const float* __restrict__ Wo, const float* __restrict__ bo,
    float* __restrict__ out)
{
    const int b  = blockIdx.z;
    const int c0 = blockIdx.y * 64;
    const int s0 = blockIdx.x * 64;

    __shared__ float Ast[32][65];  // [j'][s']
    __shared__ float Wst[32][65];  // [j'][c']

    const int tid = threadIdx.x;
    const int tx = tid & 15, ty = tid >> 4;

    u64 acc2[4][2] = {};
    const float* A = g_attn + ((size_t)b * S_ + s0) * C_;

    for (int j0 = 0; j0 < C_; j0 += 32) {
        #pragma unroll
        for (int r = 0; r < 8; r++) {
            int idx = tid + r * 256;
            int rr = idx >> 5, jj = idx & 31;
            Ast[jj][rr] = A[(size_t)rr * C_ + j0 + jj];
            Wst[jj][rr] = Wo[(size_t)(c0 + rr) * C_ + j0 + jj];
        }
        __syncthreads();

        #pragma unroll 8
        for (int jj = 0; jj < 32; jj++) {
            float a0 = Ast[jj][tx * 4 + 0], a1 = Ast[jj][tx * 4 + 1];
            float a2 = Ast[jj][tx * 4 + 2], a3 = Ast[jj][tx * 4 + 3];
            u64 a20 = pk2(a0, a1), a21 = pk2(a2, a3);
            #pragma unroll
            for (int i = 0; i < 4; i++) {
                u64 b2 = bc2(Wst[jj][ty * 4 + i]);
                fma2(acc2[i][0], b2, a20);
                fma2(acc2[i][1], b2, a21);
            }
        }
        __syncthreads();
    }

    float* ob = out + ((size_t)b * C_ + c0) * S_ + s0;
    #pragma unroll
    for (int i = 0; i < 4; i++) {
        float bi = bo[c0 + ty * 4 + i];
        float2 p0 = up2(acc2[i][0]), p1 = up2(acc2[i][1]);
        *(float4*)&ob[(size_t)(ty * 4 + i) * S_ + tx * 4] =
            make_float4(p0.x + bi, p0.y + bi, p1.x + bi, p1.y + bi);
    }
}

// ---------------------------------------------------------------------------
extern "C" void kernel_launch(void* const* d_in, const int* in_sizes, int n_in,
                              void* d_out, int out_size)
{
    const float* x  = (const float*)d_in[0];
    const float* Wq = (const float*)d_in[1];
    const float* bq = (const float*)d_in[2];
    const float* Wk = (const float*)d_in[3];
    const float* bk = (const float*)d_in[4];
    const float* Wv = (const float*)d_in[5];
    const float* bv = (const float*)d_in[6];
    const float* Wo = (const float*)d_in[7];
    const float* bo = (const float*)d_in[8];
    float* out = (float*)d_out;

    proj_kernel <<<dim3(S_ / 64, B_ * NH, 3), 256>>>(x, Wq, bq, Wk, bk, Wv, bv);
    attn_kernel <<<dim3(S_ / 64, B_ * NH),    256>>>();
    oproj_kernel<<<dim3(S_ / 64, C_ / 64, B_), 256>>>(Wo, bo, out);
}

// round 4
// speedup vs baseline: 2.7617x; 2.7270x over previous
#include <cuda_runtime.h>

#define B_  2
#define C_  512
#define NH  8
#define D_  64
#define S_  2304          // 48*48
#define SCALE 0.125f      // 1/sqrt(64)

// ---------------------------------------------------------------------------
// tf32 helpers
// ---------------------------------------------------------------------------
__device__ __forceinline__ float tf32r(float f) {
    unsigned r;
    asm("cvt.rna.tf32.f32 %0, %1;" : "=r"(r) : "f"(f));
    return __uint_as_float(r);
}
__device__ __forceinline__ void mma_tf32(float c[4],
                                         float a0, float a1, float a2, float a3,
                                         float b0, float b1) {
    asm volatile(
        "mma.sync.aligned.m16n8k8.row.col.f32.tf32.tf32.f32 "
        "{%0,%1,%2,%3}, {%4,%5,%6,%7}, {%8,%9}, {%0,%1,%2,%3};\n"
        : "+f"(c[0]), "+f"(c[1]), "+f"(c[2]), "+f"(c[3])
        : "r"(__float_as_uint(a0)), "r"(__float_as_uint(a1)),
          "r"(__float_as_uint(a2)), "r"(__float_as_uint(a3)),
          "r"(__float_as_uint(b0)), "r"(__float_as_uint(b1)));
}

// Scratch ------------------------------------------------------------------
__device__ float g_q[B_ * NH * D_ * S_];    // [b][n][d][s]
__device__ float g_k[B_ * NH * D_ * S_];    // [b][n][d][s]
__device__ float g_v[B_ * NH * S_ * D_];    // [b][n][s][d]
__device__ float g_attn[B_ * S_ * NH * D_]; // [b][s][n*64+d]

// ---------------------------------------------------------------------------
// QKV projection via tf32 mma.  m = d(64), n = s(64), k = C(512) chunk 32.
// A = W[d][c] (row-major, direct), B = x[c][s] (col-major frag, direct).
// grid (36 s-tiles, 16 bn, 3 proj), block 128 (4 warps, 2x2 of 32x32 tiles).
// ---------------------------------------------------------------------------
__global__ __launch_bounds__(128) void proj_kernel(
    const float* __restrict__ x,
    const float* __restrict__ Wq, const float* __restrict__ bq,
    const float* __restrict__ Wk, const float* __restrict__ bk,
    const float* __restrict__ Wv, const float* __restrict__ bv)
{
    __shared__ float As[64][36];   // [d][c']  A-frag stride 36 (==4 mod 32)
    __shared__ float Bs[32][72];   // [c'][s]  B-frag stride 72 (==8 mod 32)

    const int p  = blockIdx.z;
    const int bn = blockIdx.y;
    const int b  = bn >> 3, n = bn & 7;
    const int s0 = blockIdx.x * 64;

    const float* W    = (p == 0) ? Wq : (p == 1) ? Wk : Wv;
    const float* bias = (p == 0) ? bq : (p == 1) ? bk : bv;

    const int tid  = threadIdx.x;
    const int wid  = tid >> 5, lane = tid & 31;
    const int gid  = lane >> 2, tig = lane & 3;
    const int wm   = wid >> 1, wn = wid & 1;     // warp 32x32 tile coords

    const float* xb = x + (size_t)b * C_ * S_ + s0;
    const float* Wn = W + n * D_ * C_;

    float Cacc[2][4][4] = {};   // [m-atom][n-atom][reg]

    for (int k0 = 0; k0 < C_; k0 += 32) {
        // W tile: 64 rows x 32 cols = 512 float4
        #pragma unroll
        for (int r = 0; r < 4; r++) {
            int i4 = tid + r * 128;
            int dd = i4 >> 3, c4 = (i4 & 7) * 4;
            float4 v = *(const float4*)&Wn[dd * C_ + k0 + c4];
            As[dd][c4]     = tf32r(v.x); As[dd][c4 + 1] = tf32r(v.y);
            As[dd][c4 + 2] = tf32r(v.z); As[dd][c4 + 3] = tf32r(v.w);
        }
        // X tile: 32 rows x 64 cols = 512 float4
        #pragma unroll
        for (int r = 0; r < 4; r++) {
            int i4 = tid + r * 128;
            int cc = i4 >> 4, s4 = (i4 & 15) * 4;
            float4 v = *(const float4*)&xb[(size_t)(k0 + cc) * S_ + s4];
            Bs[cc][s4]     = tf32r(v.x); Bs[cc][s4 + 1] = tf32r(v.y);
            Bs[cc][s4 + 2] = tf32r(v.z); Bs[cc][s4 + 3] = tf32r(v.w);
        }
        __syncthreads();

        #pragma unroll
        for (int kk = 0; kk < 32; kk += 8) {
            float a[2][4];
            #pragma unroll
            for (int i = 0; i < 2; i++) {
                int row = wm * 32 + i * 16;
                a[i][0] = As[row + gid][kk + tig];
                a[i][1] = As[row + gid + 8][kk + tig];
                a[i][2] = As[row + gid][kk + tig + 4];
                a[i][3] = As[row + gid + 8][kk + tig + 4];
            }
            #pragma unroll
            for (int j = 0; j < 4; j++) {
                int col = wn * 32 + j * 8 + gid;
                float b0 = Bs[kk + tig][col];
                float b1 = Bs[kk + tig + 4][col];
                #pragma unroll
                for (int i = 0; i < 2; i++)
                    mma_tf32(Cacc[i][j], a[i][0], a[i][1], a[i][2], a[i][3], b0, b1);
            }
        }
        __syncthreads();
    }

    // Epilogue: rows = d = wm*32 + i*16 + gid(+8);  cols = s = wn*32 + j*8 + 2tig(+1)
    if (p < 2) {
        float* g = ((p == 0) ? g_q : g_k) + (size_t)(b * NH + n) * D_ * S_;
        #pragma unroll
        for (int i = 0; i < 2; i++) {
            int r0 = wm * 32 + i * 16 + gid;
            float bi0 = bias[n * D_ + r0], bi1 = bias[n * D_ + r0 + 8];
            #pragma unroll
            for (int j = 0; j < 4; j++) {
                int col = s0 + wn * 32 + j * 8 + 2 * tig;
                *(float2*)&g[(size_t)r0 * S_ + col] =
                    make_float2(Cacc[i][j][0] + bi0, Cacc[i][j][1] + bi0);
                *(float2*)&g[(size_t)(r0 + 8) * S_ + col] =
                    make_float2(Cacc[i][j][2] + bi1, Cacc[i][j][3] + bi1);
            }
        }
    } else {
        float* g = g_v + (size_t)(b * NH + n) * S_ * D_;   // [s][d]
        #pragma unroll
        for (int i = 0; i < 2; i++) {
            int r0 = wm * 32 + i * 16 + gid;
            float bi0 = bias[n * D_ + r0], bi1 = bias[n * D_ + r0 + 8];
            #pragma unroll
            for (int j = 0; j < 4; j++) {
                int col = s0 + wn * 32 + j * 8 + 2 * tig;
                g[(size_t)col * D_ + r0]           = Cacc[i][j][0] + bi0;
                g[(size_t)(col + 1) * D_ + r0]     = Cacc[i][j][1] + bi0;
                g[(size_t)col * D_ + r0 + 8]       = Cacc[i][j][2] + bi1;
                g[(size_t)(col + 1) * D_ + r0 + 8] = Cacc[i][j][3] + bi1;
            }
        }
    }
}

// ---------------------------------------------------------------------------
// Flash attention with tf32 mma.  q-tile 64, kv-tile 64, d = 64.
// Warp w owns q rows [w*16, w*16+16).  QK: A=Qs[q][d], B=KPs[d][k].
// PV: A=P (KPs reused, [q][k]), B=Vs[k][dv].
// Dynamic smem: Qs[64][72] + KPs[64][72] + Vs[64][72] = 55296 B.
// ---------------------------------------------------------------------------
extern __shared__ float s_attn[];

__global__ __launch_bounds__(128) void attn_kernel()
{
    float (*Qs)[72]  = (float (*)[72])(s_attn);
    float (*KPs)[72] = (float (*)[72])(s_attn + 64 * 72);
    float (*Vs)[72]  = (float (*)[72])(s_attn + 2 * 64 * 72);

    const int bn = blockIdx.y;
    const int b = bn >> 3, n = bn & 7;
    const int q0 = blockIdx.x * 64;
    const int tid = threadIdx.x;
    const int wid = tid >> 5, lane = tid & 31;
    const int gid = lane >> 2, tig = lane & 3;
    const int qr  = wid * 16;

    const float* Q = g_q + (size_t)(b * NH + n) * D_ * S_;  // [d][s]
    const float* K = g_k + (size_t)(b * NH + n) * D_ * S_;  // [d][s]
    const float* V = g_v + (size_t)(b * NH + n) * S_ * D_;  // [s][d]

    // Q transpose into Qs[q][d], scaled + tf32 (once per CTA)
    #pragma unroll
    for (int r = 0; r < 32; r++) {
        int idx = tid + r * 128;
        int dd = idx >> 6, qq = idx & 63;
        Qs[qq][dd] = tf32r(Q[(size_t)dd * S_ + q0 + qq] * SCALE);
    }

    float m0 = -1e30f, m1 = -1e30f, l0 = 0.f, l1 = 0.f;
    float O[8][4] = {};

    for (int k0 = 0; k0 < S_; k0 += 64) {
        // K tile [d][k], V tile [k][d]: 1024 float4 each
        #pragma unroll
        for (int r = 0; r < 8; r++) {
            int i4 = tid + r * 128;
            int row = i4 >> 4, c4 = (i4 & 15) * 4;
            float4 kv = *(const float4*)&K[(size_t)row * S_ + k0 + c4];
            KPs[row][c4]     = tf32r(kv.x); KPs[row][c4 + 1] = tf32r(kv.y);
            KPs[row][c4 + 2] = tf32r(kv.z); KPs[row][c4 + 3] = tf32r(kv.w);
            float4 vv = *(const float4*)&V[(size_t)(k0 + row) * D_ + c4];
            Vs[row][c4]     = tf32r(vv.x); Vs[row][c4 + 1] = tf32r(vv.y);
            Vs[row][c4 + 2] = tf32r(vv.z); Vs[row][c4 + 3] = tf32r(vv.w);
        }
        __syncthreads();

        // S = Q K^T   (warp: 16 x 64)
        float Sc[8][4] = {};
        #pragma unroll
        for (int kk = 0; kk < 64; kk += 8) {
            float a0 = Qs[qr + gid][kk + tig];
            float a1 = Qs[qr + gid + 8][kk + tig];
            float a2 = Qs[qr + gid][kk + tig + 4];
            float a3 = Qs[qr + gid + 8][kk + tig + 4];
            #pragma unroll
            for (int j = 0; j < 8; j++) {
                float b0 = KPs[kk + tig][j * 8 + gid];
                float b1 = KPs[kk + tig + 4][j * 8 + gid];
                mma_tf32(Sc[j], a0, a1, a2, a3, b0, b1);
            }
        }

        // online softmax: thread rows qr+gid (regs 0,1), qr+gid+8 (regs 2,3)
        float r0 = -1e30f, r1 = -1e30f;
        #pragma unroll
        for (int j = 0; j < 8; j++) {
            r0 = fmaxf(r0, fmaxf(Sc[j][0], Sc[j][1]));
            r1 = fmaxf(r1, fmaxf(Sc[j][2], Sc[j][3]));
        }
        r0 = fmaxf(r0, __shfl_xor_sync(0xffffffffu, r0, 1));
        r0 = fmaxf(r0, __shfl_xor_sync(0xffffffffu, r0, 2));
        r1 = fmaxf(r1, __shfl_xor_sync(0xffffffffu, r1, 1));
        r1 = fmaxf(r1, __shfl_xor_sync(0xffffffffu, r1, 2));

        float mn0 = fmaxf(m0, r0), mn1 = fmaxf(m1, r1);
        float corr0 = __expf(m0 - mn0), corr1 = __expf(m1 - mn1);
        float sum0 = 0.f, sum1 = 0.f;
        #pragma unroll
        for (int j = 0; j < 8; j++) {
            Sc[j][0] = __expf(Sc[j][0] - mn0);
            Sc[j][1] = __expf(Sc[j][1] - mn0);
            Sc[j][2] = __expf(Sc[j][2] - mn1);
            Sc[j][3] = __expf(Sc[j][3] - mn1);
            sum0 += Sc[j][0] + Sc[j][1];
            sum1 += Sc[j][2] + Sc[j][3];
        }
        sum0 += __shfl_xor_sync(0xffffffffu, sum0, 1);
        sum0 += __shfl_xor_sync(0xffffffffu, sum0, 2);
        sum1 += __shfl_xor_sync(0xffffffffu, sum1, 1);
        sum1 += __shfl_xor_sync(0xffffffffu, sum1, 2);
        l0 = l0 * corr0 + sum0;  m0 = mn0;
        l1 = l1 * corr1 + sum1;  m1 = mn1;
        #pragma unroll
        for (int j = 0; j < 8; j++) {
            O[j][0] *= corr0; O[j][1] *= corr0;
            O[j][2] *= corr1; O[j][3] *= corr1;
        }

        __syncthreads();   // all warps finished reading K from KPs
        // P -> KPs as A-layout [q][k] (tf32)
        #pragma unroll
        for (int j = 0; j < 8; j++) {
            int col = j * 8 + 2 * tig;
            *(float2*)&KPs[qr + gid][col] =
                make_float2(tf32r(Sc[j][0]), tf32r(Sc[j][1]));
            *(float2*)&KPs[qr + gid + 8][col] =
                make_float2(tf32r(Sc[j][2]), tf32r(Sc[j][3]));
        }
        __syncthreads();

        // O += P @ V
        #pragma unroll
        for (int kk = 0; kk < 64; kk += 8) {
            float a0 = KPs[qr + gid][kk + tig];
            float a1 = KPs[qr + gid + 8][kk + tig];
            float a2 = KPs[qr + gid][kk + tig + 4];
            float a3 = KPs[qr + gid + 8][kk + tig + 4];
            #pragma unroll
            for (int j = 0; j < 8; j++) {
                float b0 = Vs[kk + tig][j * 8 + gid];
                float b1 = Vs[kk + tig + 4][j * 8 + gid];
                mma_tf32(O[j], a0, a1, a2, a3, b0, b1);
            }
        }
        __syncthreads();
    }

    // epilogue
    float inv0 = 1.f / l0, inv1 = 1.f / l1;
    float* A = g_attn + ((size_t)b * S_ + q0) * (NH * D_) + n * D_;
    #pragma unroll
    for (int j = 0; j < 8; j++) {
        int col = j * 8 + 2 * tig;
        *(float2*)&A[(size_t)(qr + gid) * (NH * D_) + col] =
            make_float2(O[j][0] * inv0, O[j][1] * inv0);
        *(float2*)&A[(size_t)(qr + gid + 8) * (NH * D_) + col] =
            make_float2(O[j][2] * inv1, O[j][3] * inv1);
    }
}

// ---------------------------------------------------------------------------
// Output projection via tf32 mma.  m = c(64), n = s(64), k = 512 chunk 32.
// A = Wo[c][j] direct;  B = attn[s][j] -> transposed smem store Bs[j][s].
// ---------------------------------------------------------------------------
__global__ __launch_bounds__(128) void oproj_kernel(
    const float* __restrict__ Wo, const float* __restrict__ bo,
    float* __restrict__ out)
{
    __shared__ float As[64][36];   // [c][j']
    __shared__ float Bs[32][72];   // [j'][s]

    const int b  = blockIdx.z;
    const int c0 = blockIdx.y * 64;
    const int s0 = blockIdx.x * 64;

    const int tid = threadIdx.x;
    const int wid = tid >> 5, lane = tid & 31;
    const int gid = lane >> 2, tig = lane & 3;
    const int wm  = wid >> 1, wn = wid & 1;

    const float* A = g_attn + ((size_t)b * S_ + s0) * C_;

    float Cacc[2][4][4] = {};

    for (int j0 = 0; j0 < C_; j0 += 32) {
        #pragma unroll
        for (int r = 0; r < 4; r++) {
            int i4 = tid + r * 128;
            int cc = i4 >> 3, j4 = (i4 & 7) * 4;
            float4 v = *(const float4*)&Wo[(size_t)(c0 + cc) * C_ + j0 + j4];
            As[cc][j4]     = tf32r(v.x); As[cc][j4 + 1] = tf32r(v.y);
            As[cc][j4 + 2] = tf32r(v.z); As[cc][j4 + 3] = tf32r(v.w);
        }
        #pragma unroll
        for (int r = 0; r < 16; r++) {          // attn tile transposed
            int idx = tid + r * 128;
            int ss = idx >> 5, jj = idx & 31;
            Bs[jj][ss] = tf32r(A[(size_t)ss * C_ + j0 + jj]);
        }
        __syncthreads();

        #pragma unroll
        for (int kk = 0; kk < 32; kk += 8) {
            float a[2][4];
            #pragma unroll
            for (int i = 0; i < 2; i++) {
                int row = wm * 32 + i * 16;
                a[i][0] = As[row + gid][kk + tig];
                a[i][1] = As[row + gid + 8][kk + tig];
                a[i][2] = As[row + gid][kk + tig + 4];
                a[i][3] = As[row + gid + 8][kk + tig + 4];
            }
            #pragma unroll
            for (int j = 0; j < 4; j++) {
                int col = wn * 32 + j * 8 + gid;
                float b0 = Bs[kk + tig][col];
                float b1 = Bs[kk + tig + 4][col];
                #pragma unroll
                for (int i = 0; i < 2; i++)
                    mma_tf32(Cacc[i][j], a[i][0], a[i][1], a[i][2], a[i][3], b0, b1);
            }
        }
        __syncthreads();
    }

    float* ob = out + ((size_t)b * C_ + c0) * S_ + s0;
    #pragma unroll
    for (int i = 0; i < 2; i++) {
        int r0 = wm * 32 + i * 16 + gid;
        float bi0 = bo[c0 + r0], bi1 = bo[c0 + r0 + 8];
        #pragma unroll
        for (int j = 0; j < 4; j++) {
            int col = wn * 32 + j * 8 + 2 * tig;
            *(float2*)&ob[(size_t)r0 * S_ + col] =
                make_float2(Cacc[i][j][0] + bi0, Cacc[i][j][1] + bi0);
            *(float2*)&ob[(size_t)(r0 + 8) * S_ + col] =
                make_float2(Cacc[i][j][2] + bi1, Cacc[i][j][3] + bi1);
        }
    }
}

// ---------------------------------------------------------------------------
extern "C" void kernel_launch(void* const* d_in, const int* in_sizes, int n_in,
                              void* d_out, int out_size)
{
    const float* x  = (const float*)d_in[0];
    const float* Wq = (const float*)d_in[1];
    const float* bq = (const float*)d_in[2];
    const float* Wk = (const float*)d_in[3];
    const float* bk = (const float*)d_in[4];
    const float* Wv = (const float*)d_in[5];
    const float* bv = (const float*)d_in[6];
    const float* Wo = (const float*)d_in[7];
    const float* bo = (const float*)d_in[8];
    float* out = (float*)d_out;

    const int attn_smem = 3 * 64 * 72 * sizeof(float);   // 55296
    cudaFuncSetAttribute(attn_kernel,
                         cudaFuncAttributeMaxDynamicSharedMemorySize, attn_smem);

    proj_kernel <<<dim3(S_ / 64, B_ * NH, 3), 128>>>(x, Wq, bq, Wk, bk, Wv, bv);
    attn_kernel <<<dim3(S_ / 64, B_ * NH), 128, attn_smem>>>();
    oproj_kernel<<<dim3(S_ / 64, C_ / 64, B_), 128>>>(Wo, bo, out);
}